// round 10
// baseline (speedup 1.0000x reference)
#include <cuda_runtime.h>
#include <cuda_fp16.h>
#include <math.h>
#include <stdint.h>

#define DD 128            // embedding dim
#define KK 512            // num centers
#define BM 64             // rows per block tile
#define THREADS 256

// ---- smem layout (bytes) ----
// A: 2 fp16 split images of X tile, each [64 rows][136 half] (272B rows; 272%128=16
//    so LDSM 8-row tiles hit distinct bank quads)
#define A_SPLIT_BYTES (64 * 272)           // 17408
#define SM_A      0                        // 2 * 17408 = 34816
// B: DOUBLE-buffered phase = [2 splits][64 n][72 half] (144B rows)
#define B_IMG_BYTES (64 * 144)             // 9216
#define B_PHASE_BYTES (2 * B_IMG_BYTES)    // 18432
#define SM_B      34816                    // 2 * 18432 = 36864 -> ends 71680
#define SM_C2     71680                    // 512 f32  -> 73728
#define SM_X2     73728                    // 64 f32   -> 73984
#define SM_COLPK  73984                    // 512 u64  -> 78080
#define SM_ROWRED 78080                    // 128 f32  -> 78592
#define SM_X2P    78592                    // 256 f32  -> 79616
#define SM_LOSS   SM_B                     // overlay: loss written after B is dead
#define SMEM_BYTES 79616

typedef unsigned long long ull;

__device__ ull   g_center_min[KK];
__device__ float g_c2[KK];
__device__ float g_loss_partial[4096];
// B global images: [phase 16][split 2][n 64][36 u32]; phase = (nchunk, khalf)
__device__ uint32_t g_Bimg[16 * 2 * 64 * 36];

// ---------------------------------------------------------------------------
__device__ __forceinline__ uint32_t smem_u32(const void* p) {
    uint32_t a;
    asm("{ .reg .u64 t; cvta.to.shared.u64 t, %1; cvt.u32.u64 %0, t; }"
        : "=r"(a) : "l"(p));
    return a;
}
__device__ __forceinline__ void ldsm4(uint32_t r[4], uint32_t addr) {
    asm volatile("ldmatrix.sync.aligned.m8n8.x4.shared.b16 {%0,%1,%2,%3}, [%4];"
                 : "=r"(r[0]), "=r"(r[1]), "=r"(r[2]), "=r"(r[3]) : "r"(addr));
}
__device__ __forceinline__ void mma_fp16(float acc[4], const uint32_t a[4],
                                         uint32_t b0, uint32_t b1) {
    asm("mma.sync.aligned.m16n8k16.row.col.f32.f16.f16.f32 "
        "{%0,%1,%2,%3}, {%4,%5,%6,%7}, {%8,%9}, {%0,%1,%2,%3};"
        : "+f"(acc[0]), "+f"(acc[1]), "+f"(acc[2]), "+f"(acc[3])
        : "r"(a[0]), "r"(a[1]), "r"(a[2]), "r"(a[3]), "r"(b0), "r"(b1));
}
__device__ __forceinline__ void cpa16(uint32_t dst, const void* src) {
    asm volatile("cp.async.cg.shared.global [%0], [%1], 16;"
                 :: "r"(dst), "l"(src));
}
__device__ __forceinline__ void cpa_commit() {
    asm volatile("cp.async.commit_group;" ::: "memory");
}
__device__ __forceinline__ void cpa_wait1() {
    asm volatile("cp.async.wait_group 1;" ::: "memory");
}
// split one fp32 into 2 fp16 (exact residual)
__device__ __forceinline__ void split2(float v, __half& h0, __half& h1) {
    h0 = __float2half_rn(v);
    h1 = __float2half_rn(v - __half2float(h0));
}

// ---------------------------------------------------------------------------
// Init: c2, argmin accumulators, pre-split & pre-scaled (x2) B images.
// ---------------------------------------------------------------------------
__global__ void cl_init_kernel(const float* __restrict__ C) {
    int t = blockIdx.x * 256 + threadIdx.x;      // 0 .. 32767
    int k = t >> 6;                              // center
    int dp = (t & 63) * 2;                       // d, d+1
    if (k >= KK) return;

    float a = 2.f * C[(size_t)k * DD + dp];
    float b = 2.f * C[(size_t)k * DD + dp + 1];
    __half a0, a1, b0, b1;
    split2(a, a0, a1);
    split2(b, b0, b1);
    int phase = (k >> 6) * 2 + (dp >> 6);        // (nchunk, khalf)
    int n = k & 63;
    int dl = dp & 63;
    uint32_t idx = (uint32_t)phase * (2 * 64 * 36) + n * 36 + (dl >> 1);
    __half2 p;
    p.x = a0; p.y = b0; g_Bimg[idx]           = *(uint32_t*)&p;
    p.x = a1; p.y = b1; g_Bimg[idx + 64 * 36] = *(uint32_t*)&p;

    if (dp == 0) {
        const float* row = C + (size_t)k * DD;
        float s = 0.f;
        #pragma unroll 8
        for (int d = 0; d < DD; ++d) { float v = row[d]; s = fmaf(v, v, s); }
        g_c2[k] = s;
        g_center_min[k] = 0xFFFFFFFFFFFFFFFFULL;
    }
}

// ---------------------------------------------------------------------------
__global__ void __launch_bounds__(THREADS, 2)
cl_main_kernel(const float* __restrict__ X, int N) {
    extern __shared__ char sm[];
    const uint32_t smb = smem_u32(sm);

    const int tid = threadIdx.x;
    const int wid = tid >> 5, lid = tid & 31;
    const int wm = wid & 3, wn = wid >> 2;       // 4 M-warps (16 rows) x 2 N-warps
    const int row0 = blockIdx.x * BM;

    float* c2s    = (float*)(sm + SM_C2);
    float* x2s    = (float*)(sm + SM_X2);
    ull*   colpk  = (ull*)(sm + SM_COLPK);
    float* rowred = (float*)(sm + SM_ROWRED);
    float* loss_s = (float*)(sm + SM_LOSS);
    float* x2p    = (float*)(sm + SM_X2P);

    #pragma unroll
    for (int i = 0; i < 2; ++i) {
        c2s[tid + i * 256] = g_c2[tid + i * 256];
        colpk[tid + i * 256] = 0xFFFFFFFFFFFFFFFFULL;
    }

    // ---- X tile: load, 2-way fp16 split into A images, row-norm partials ----
    // 4 threads per row, 32 floats each
    {
        int m = tid >> 2, qt = tid & 3;
        int gr = row0 + m;
        bool valid = gr < N;
        const float4* src = (const float4*)(X + (size_t)gr * DD + qt * 32);
        char* arow = sm + SM_A + m * 272 + qt * 64;   // byte base for this quarter-row
        float s2 = 0.f;
        #pragma unroll
        for (int q = 0; q < 8; ++q) {
            float4 v = valid ? src[q] : make_float4(0.f, 0.f, 0.f, 0.f);
            s2 = fmaf(v.x, v.x, s2); s2 = fmaf(v.y, v.y, s2);
            s2 = fmaf(v.z, v.z, s2); s2 = fmaf(v.w, v.w, s2);
            __half s0[4], s1[4];
            split2(v.x, s0[0], s1[0]);
            split2(v.y, s0[1], s1[1]);
            split2(v.z, s0[2], s1[2]);
            split2(v.w, s0[3], s1[3]);
            __half2 p;
            #pragma unroll
            for (int j = 0; j < 2; ++j) {
                int off = q * 8 + j * 4;
                p.x = s0[2*j]; p.y = s0[2*j+1];
                *(uint32_t*)(arow + off) = *(uint32_t*)&p;
                p.x = s1[2*j]; p.y = s1[2*j+1];
                *(uint32_t*)(arow + A_SPLIT_BYTES + off) = *(uint32_t*)&p;
            }
        }
        x2p[tid] = s2;
    }
    __syncthreads();
    if (tid < BM)
        x2s[tid] = (row0 + tid < N)
                   ? (x2p[4 * tid] + x2p[4 * tid + 1] + x2p[4 * tid + 2] + x2p[4 * tid + 3])
                   : INFINITY;

    // ---- prime phase 0 into buf0 (1152 16B lines) ----
    {
        const char* gb = (const char*)g_Bimg;
        uint32_t dst = smb + SM_B;
        #pragma unroll
        for (int it = 0; it < 5; ++it) {
            int idx = tid + it * 256;
            if (idx < 1152) cpa16(dst + idx * 16, gb + idx * 16);
        }
        cpa_commit();
    }

    // lane decomposition for fragment addressing
    const int l8 = lid & 7, lq = (lid >> 3) & 1, lh = lid >> 4;
    const uint32_t aRow = smb + SM_A + (uint32_t)(wm * 16 + lq * 8 + l8) * 272 + lh * 16;
    const uint32_t bRow = smb + SM_B + (uint32_t)(lq * 8 + l8) * 144 + lh * 16;

    // per-thread state: accumulators + persistent row-min + x2/rowid cache
    float acc[4][4];
    const int q = lid >> 2, r4 = lid & 3;
    float xr[2]; int rowid[2]; float rm[2];
    #pragma unroll
    for (int hf = 0; hf < 2; ++hf) {
        rowid[hf] = wm * 16 + hf * 8 + q;
        rm[hf] = INFINITY;
    }
    __syncthreads();   // x2s ready
    #pragma unroll
    for (int hf = 0; hf < 2; ++hf) xr[hf] = x2s[rowid[hf]];

    for (int p = 0; p < 16; ++p) {
        const int nc = p >> 1, half = p & 1;
        if (half == 0) {
            #pragma unroll
            for (int ni = 0; ni < 4; ++ni)
                #pragma unroll
                for (int c = 0; c < 4; ++c) acc[ni][c] = 0.f;
        }
        __syncthreads();   // all warps done reading buf[(p+1)&1] (phase p-1)
        // prefetch phase p+1 into buf[(p+1)&1]
        if (p + 1 < 16) {
            const char* gb = (const char*)g_Bimg + (size_t)(p + 1) * B_PHASE_BYTES;
            uint32_t dst = smb + SM_B + ((p + 1) & 1) * B_PHASE_BYTES;
            #pragma unroll
            for (int it = 0; it < 5; ++it) {
                int idx = tid + it * 256;
                if (idx < 1152) cpa16(dst + idx * 16, gb + idx * 16);
            }
        }
        cpa_commit();
        cpa_wait1();       // phase p resident (issued a full phase ago)
        __syncthreads();

        // ---- compute: K-half = 4 ksteps of 16 ----
        const uint32_t aP = aRow + half * 128;
        const uint32_t bP = bRow + (p & 1) * B_PHASE_BYTES;
        #pragma unroll
        for (int kk = 0; kk < 4; ++kk) {
            uint32_t a[2][4];
            #pragma unroll
            for (int s = 0; s < 2; ++s)
                ldsm4(a[s], aP + s * A_SPLIT_BYTES + kk * 32);
            #pragma unroll
            for (int sb = 0; sb < 2; ++sb) {
                uint32_t br[2][4];
                #pragma unroll
                for (int np = 0; np < 2; ++np)
                    ldsm4(br[np], bP + sb * B_IMG_BYTES + (wn * 32 + np * 16) * 144 + kk * 32);
                const int nsa = (sb == 0) ? 2 : 1;   // products: 00, 10, 01
                #pragma unroll
                for (int sa = 0; sa < 2; ++sa) {
                    if (sa < nsa) {
                        #pragma unroll
                        for (int np = 0; np < 2; ++np) {
                            mma_fp16(acc[np * 2],     a[sa], br[np][0], br[np][2]);
                            mma_fp16(acc[np * 2 + 1], a[sa], br[np][1], br[np][3]);
                        }
                    }
                }
            }
        }

        // ---- per-chunk epilogue (after second K-half): colpk atomics only ----
        if (half == 1) {
            #pragma unroll
            for (int ni = 0; ni < 4; ++ni)
                #pragma unroll
                for (int j = 0; j < 2; ++j) {
                    int c = nc * 64 + wn * 32 + ni * 8 + r4 * 2 + j;
                    float c2v = c2s[c];
                    ull best = 0xFFFFFFFFFFFFFFFFULL;
                    #pragma unroll
                    for (int hf = 0; hf < 2; ++hf) {
                        float d2 = fmaxf(xr[hf] + c2v - acc[ni][hf * 2 + j], 1e-12f);
                        rm[hf] = fminf(rm[hf], d2);
                        ull pk = ((ull)__float_as_uint(d2) << 32) |
                                 (unsigned int)(row0 + rowid[hf]);
                        best = (pk < best) ? pk : best;
                    }
                    if (best < colpk[c]) atomicMin(&colpk[c], best);
                }
        }
    }

    // ---- single deferred row-min reduction ----
    #pragma unroll
    for (int hf = 0; hf < 2; ++hf) {
        float v = rm[hf];
        v = fminf(v, __shfl_xor_sync(0xFFFFFFFFu, v, 1));
        v = fminf(v, __shfl_xor_sync(0xFFFFFFFFu, v, 2));
        if (r4 == 0)
            rowred[wn * 64 + rowid[hf]] = v;
    }
    __syncthreads();   // rowred complete; B now dead -> loss_s may overlay it

    if (tid < BM)
        loss_s[tid] = (row0 + tid < N)
                      ? sqrtf(fminf(rowred[tid], rowred[64 + tid])) : 0.f;
    __syncthreads();
    #pragma unroll
    for (int i = 0; i < 2; ++i) {
        int k = tid + i * 256;
        atomicMin(&g_center_min[k], colpk[k]);
    }
    if (tid == 0) {
        float s = 0.f;
        for (int i = 0; i < BM; ++i) s += loss_s[i];
        g_loss_partial[blockIdx.x] = s;
    }
}

// ---------------------------------------------------------------------------
// Finalize: deterministic loss reduction + centers copy + rep_ids
// out layout: [centers 512*128][rep_ids 512][loss 1]
// ---------------------------------------------------------------------------
__global__ void cl_fin_kernel(const float* __restrict__ C, float* __restrict__ out, int nb) {
    int b = blockIdx.x;
    int tid = threadIdx.x;
    if (b == 0) {
        __shared__ float s[256];
        float acc = 0.f;
        for (int i = tid; i < nb; i += 256) acc += g_loss_partial[i];
        s[tid] = acc;
        __syncthreads();
        if (tid == 0) {
            float tot = 0.f;
            for (int i = 0; i < 256; ++i) tot += s[i];
            out[KK * DD + KK] = tot;
        }
    } else if (b <= 256) {
        int idx = (b - 1) * 256 + tid;
        out[idx] = C[idx];
    } else {
        for (int k = tid; k < KK; k += 256) {
            out[KK * DD + k] =
                (float)(unsigned int)(g_center_min[k] & 0xFFFFFFFFULL);
        }
    }
}

// 4th launch: keeps launch-count parity with prior rounds' ncu capture.
__global__ void cl_nop_kernel() {}

// ---------------------------------------------------------------------------
extern "C" void kernel_launch(void* const* d_in, const int* in_sizes, int n_in,
                              void* d_out, int out_size) {
    const float* X = (const float*)d_in[0];
    const float* C = (const float*)d_in[1];
    float* out = (float*)d_out;

    int N = in_sizes[0] / DD;
    int nb = (N + BM - 1) / BM;

    cudaFuncSetAttribute(cl_main_kernel,
                         cudaFuncAttributeMaxDynamicSharedMemorySize, SMEM_BYTES);

    cl_init_kernel<<<128, 256>>>(C);
    cl_main_kernel<<<nb, THREADS, SMEM_BYTES>>>(X, N);
    cl_fin_kernel<<<258, 256>>>(C, out, nb);
    cl_nop_kernel<<<1, 32>>>();
}

// round 11
// speedup vs baseline: 1.3373x; 1.3373x over previous
#include <cuda_runtime.h>
#include <cuda_fp16.h>
#include <math.h>
#include <stdint.h>

#define DD 128            // embedding dim
#define KK 512            // num centers
#define BM 128            // rows per block tile
#define THREADS 256

// ---- smem layout (bytes) ----
// A: 2 fp16 split images of X tile, each [128 rows][136 half] (272B rows; 272%128=16
//    so LDSM 8-row tiles hit distinct bank quads)
#define A_SPLIT_BYTES (128 * 272)          // 34816
#define SM_A      0                        // 2 * 34816 = 69632
// B: SINGLE-buffered full-K phase = [2 splits][64 n][136 half] (272B rows)
#define B_IMG_BYTES (64 * 272)             // 17408 per split
#define B_PHASE_BYTES (2 * B_IMG_BYTES)    // 34816
#define SM_B      69632                    // ends 104448
#define SM_C2     104448                   // 512 f32  -> 106496
#define SM_X2     106496                   // 128 f32  -> 107008
#define SM_COLPK  107008                   // 512 u64  -> 111104
#define SM_ROWRED 111104                   // 256 f32  -> 112128 (end-of-kernel only)
#define SM_X2P    SM_ROWRED                // overlay: X2P used only in prologue
#define SM_LOSS   SM_B                     // overlay: loss written after B is dead
#define SMEM_BYTES 112128

typedef unsigned long long ull;

__device__ ull   g_center_min[KK];
__device__ float g_c2[KK];
__device__ float g_loss_partial[4096];
// B global images: [nchunk 8][split 2][n 64][68 u32]; full-K rows (272B)
__device__ uint32_t g_Bimg[8 * 2 * 64 * 68];

// ---------------------------------------------------------------------------
__device__ __forceinline__ uint32_t smem_u32(const void* p) {
    uint32_t a;
    asm("{ .reg .u64 t; cvta.to.shared.u64 t, %1; cvt.u32.u64 %0, t; }"
        : "=r"(a) : "l"(p));
    return a;
}
__device__ __forceinline__ void ldsm4(uint32_t r[4], uint32_t addr) {
    asm volatile("ldmatrix.sync.aligned.m8n8.x4.shared.b16 {%0,%1,%2,%3}, [%4];"
                 : "=r"(r[0]), "=r"(r[1]), "=r"(r[2]), "=r"(r[3]) : "r"(addr));
}
__device__ __forceinline__ void mma_fp16(float acc[4], const uint32_t a[4],
                                         uint32_t b0, uint32_t b1) {
    asm("mma.sync.aligned.m16n8k16.row.col.f32.f16.f16.f32 "
        "{%0,%1,%2,%3}, {%4,%5,%6,%7}, {%8,%9}, {%0,%1,%2,%3};"
        : "+f"(acc[0]), "+f"(acc[1]), "+f"(acc[2]), "+f"(acc[3])
        : "r"(a[0]), "r"(a[1]), "r"(a[2]), "r"(a[3]), "r"(b0), "r"(b1));
}
__device__ __forceinline__ void cpa16(uint32_t dst, const void* src) {
    asm volatile("cp.async.cg.shared.global [%0], [%1], 16;"
                 :: "r"(dst), "l"(src));
}
__device__ __forceinline__ void cpa_commit() {
    asm volatile("cp.async.commit_group;" ::: "memory");
}
__device__ __forceinline__ void cpa_wait0() {
    asm volatile("cp.async.wait_group 0;" ::: "memory");
}
// split one fp32 into 2 fp16 (exact residual)
__device__ __forceinline__ void split2(float v, __half& h0, __half& h1) {
    h0 = __float2half_rn(v);
    h1 = __float2half_rn(v - __half2float(h0));
}

// ---------------------------------------------------------------------------
// Init: c2, argmin accumulators, pre-split & pre-scaled (x2) B images.
// ---------------------------------------------------------------------------
__global__ void cl_init_kernel(const float* __restrict__ C) {
    int t = blockIdx.x * 256 + threadIdx.x;      // 0 .. 32767
    int k = t >> 6;                              // center
    int dp = (t & 63) * 2;                       // d, d+1
    if (k >= KK) return;

    float a = 2.f * C[(size_t)k * DD + dp];
    float b = 2.f * C[(size_t)k * DD + dp + 1];
    __half a0, a1, b0, b1;
    split2(a, a0, a1);
    split2(b, b0, b1);
    int nc = k >> 6;                             // center chunk
    int n = k & 63;
    uint32_t idx = (uint32_t)nc * (2 * 64 * 68) + n * 68 + (dp >> 1);
    __half2 p;
    p.x = a0; p.y = b0; g_Bimg[idx]           = *(uint32_t*)&p;
    p.x = a1; p.y = b1; g_Bimg[idx + 64 * 68] = *(uint32_t*)&p;

    if (dp == 0) {
        const float* row = C + (size_t)k * DD;
        float s = 0.f;
        #pragma unroll 8
        for (int d = 0; d < DD; ++d) { float v = row[d]; s = fmaf(v, v, s); }
        g_c2[k] = s;
        g_center_min[k] = 0xFFFFFFFFFFFFFFFFULL;
    }
}

// ---------------------------------------------------------------------------
__global__ void __launch_bounds__(THREADS, 2)
cl_main_kernel(const float* __restrict__ X, int N) {
    extern __shared__ char sm[];
    const uint32_t smb = smem_u32(sm);

    const int tid = threadIdx.x;
    const int wid = tid >> 5, lid = tid & 31;
    const int wm = wid & 3, wn = wid >> 2;       // 4 M-warps x 2 N-warps
    const int row0 = blockIdx.x * BM;

    float* c2s    = (float*)(sm + SM_C2);
    float* x2s    = (float*)(sm + SM_X2);
    ull*   colpk  = (ull*)(sm + SM_COLPK);
    float* rowred = (float*)(sm + SM_ROWRED);
    float* loss_s = (float*)(sm + SM_LOSS);
    float* x2p    = (float*)(sm + SM_X2P);

    #pragma unroll
    for (int i = 0; i < 2; ++i) {
        c2s[tid + i * 256] = g_c2[tid + i * 256];
        colpk[tid + i * 256] = 0xFFFFFFFFFFFFFFFFULL;
    }

    // ---- X tile: load, 2-way fp16 split into A images, row-norm partials ----
    {
        int m = tid >> 1, h = tid & 1;
        int gr = row0 + m;
        bool valid = gr < N;
        const float4* src = (const float4*)(X + (size_t)gr * DD + h * 64);
        char* arow = sm + SM_A + m * 272 + h * 128;   // byte base for this half-row
        float s2 = 0.f;
        #pragma unroll
        for (int q = 0; q < 16; ++q) {
            float4 v = valid ? src[q] : make_float4(0.f, 0.f, 0.f, 0.f);
            s2 = fmaf(v.x, v.x, s2); s2 = fmaf(v.y, v.y, s2);
            s2 = fmaf(v.z, v.z, s2); s2 = fmaf(v.w, v.w, s2);
            __half s0[4], s1[4];
            split2(v.x, s0[0], s1[0]);
            split2(v.y, s0[1], s1[1]);
            split2(v.z, s0[2], s1[2]);
            split2(v.w, s0[3], s1[3]);
            __half2 p;
            #pragma unroll
            for (int j = 0; j < 2; ++j) {
                int off = q * 8 + j * 4;
                p.x = s0[2*j]; p.y = s0[2*j+1];
                *(uint32_t*)(arow + off) = *(uint32_t*)&p;
                p.x = s1[2*j]; p.y = s1[2*j+1];
                *(uint32_t*)(arow + A_SPLIT_BYTES + off) = *(uint32_t*)&p;
            }
        }
        x2p[tid] = s2;
    }
    __syncthreads();
    if (tid < BM)
        x2s[tid] = (row0 + tid < N) ? (x2p[2 * tid] + x2p[2 * tid + 1]) : INFINITY;

    // lane decomposition for fragment addressing
    const int l8 = lid & 7, lq = (lid >> 3) & 1, lh = lid >> 4;
    const uint32_t aRow = smb + SM_A + (uint32_t)(wm * 32 + lq * 8 + l8) * 272 + lh * 16;
    const uint32_t bRow = smb + SM_B + (uint32_t)(lq * 8 + l8) * 272 + lh * 16;

    // per-thread state: accumulators + persistent row-min + x2/rowid cache
    float acc[2][4][4];
    const int q = lid >> 2, r4 = lid & 3;
    float xr[2][2]; int rowid[2][2]; float rm[2][2];
    #pragma unroll
    for (int mi = 0; mi < 2; ++mi)
        #pragma unroll
        for (int hf = 0; hf < 2; ++hf) {
            rowid[mi][hf] = wm * 32 + mi * 16 + hf * 8 + q;
            rm[mi][hf] = INFINITY;
        }
    __syncthreads();   // x2s ready (also: X2P overlay safe before ROWRED use)
    #pragma unroll
    for (int mi = 0; mi < 2; ++mi)
        #pragma unroll
        for (int hf = 0; hf < 2; ++hf) xr[mi][hf] = x2s[rowid[mi][hf]];

    for (int nc = 0; nc < 8; ++nc) {
        #pragma unroll
        for (int mi = 0; mi < 2; ++mi)
            #pragma unroll
            for (int ni = 0; ni < 4; ++ni)
                #pragma unroll
                for (int c = 0; c < 4; ++c) acc[mi][ni][c] = 0.f;

        __syncthreads();   // all warps done reading B from chunk nc-1
        // load chunk nc (2176 16B lines)
        {
            const char* gb = (const char*)g_Bimg + (size_t)nc * B_PHASE_BYTES;
            uint32_t dst = smb + SM_B;
            #pragma unroll
            for (int it = 0; it < 9; ++it) {
                int idx = tid + it * 256;
                if (idx < 2176) cpa16(dst + idx * 16, gb + idx * 16);
            }
        }
        cpa_commit();
        cpa_wait0();
        __syncthreads();

        // ---- compute: full K = 8 ksteps of 16 ----
        #pragma unroll
        for (int kk = 0; kk < 8; ++kk) {
            uint32_t a[2][2][4];
            #pragma unroll
            for (int s = 0; s < 2; ++s)
                #pragma unroll
                for (int mi = 0; mi < 2; ++mi)
                    ldsm4(a[s][mi], aRow + s * A_SPLIT_BYTES + mi * (16 * 272) + kk * 32);
            #pragma unroll
            for (int sb = 0; sb < 2; ++sb) {
                uint32_t br[2][4];
                #pragma unroll
                for (int np = 0; np < 2; ++np)
                    ldsm4(br[np], bRow + sb * B_IMG_BYTES + (wn * 32 + np * 16) * 272 + kk * 32);
                const int nsa = (sb == 0) ? 2 : 1;   // products: 00, 10, 01
                #pragma unroll
                for (int sa = 0; sa < 2; ++sa) {
                    if (sa < nsa) {
                        #pragma unroll
                        for (int mi = 0; mi < 2; ++mi)
                            #pragma unroll
                            for (int np = 0; np < 2; ++np) {
                                mma_fp16(acc[mi][np * 2],     a[sa][mi], br[np][0], br[np][2]);
                                mma_fp16(acc[mi][np * 2 + 1], a[sa][mi], br[np][1], br[np][3]);
                            }
                    }
                }
            }
        }

        // ---- per-chunk epilogue: colpk atomics + running row-min ----
        #pragma unroll
        for (int ni = 0; ni < 4; ++ni)
            #pragma unroll
            for (int j = 0; j < 2; ++j) {
                int c = nc * 64 + wn * 32 + ni * 8 + r4 * 2 + j;
                float c2v = c2s[c];
                ull best = 0xFFFFFFFFFFFFFFFFULL;
                #pragma unroll
                for (int mi = 0; mi < 2; ++mi)
                    #pragma unroll
                    for (int hf = 0; hf < 2; ++hf) {
                        float d2 = fmaxf(xr[mi][hf] + c2v - acc[mi][ni][hf * 2 + j],
                                         1e-12f);
                        rm[mi][hf] = fminf(rm[mi][hf], d2);
                        ull pk = ((ull)__float_as_uint(d2) << 32) |
                                 (unsigned int)(row0 + rowid[mi][hf]);
                        best = (pk < best) ? pk : best;
                    }
                if (best < colpk[c]) atomicMin(&colpk[c], best);
            }
    }

    // ---- single deferred row-min reduction ----
    #pragma unroll
    for (int mi = 0; mi < 2; ++mi)
        #pragma unroll
        for (int hf = 0; hf < 2; ++hf) {
            float v = rm[mi][hf];
            v = fminf(v, __shfl_xor_sync(0xFFFFFFFFu, v, 1));
            v = fminf(v, __shfl_xor_sync(0xFFFFFFFFu, v, 2));
            if (r4 == 0)
                rowred[wn * 128 + rowid[mi][hf]] = v;
        }
    __syncthreads();   // rowred complete; B now dead -> loss_s may overlay it

    if (tid < BM)
        loss_s[tid] = (row0 + tid < N)
                      ? sqrtf(fminf(rowred[tid], rowred[128 + tid])) : 0.f;
    __syncthreads();
    #pragma unroll
    for (int i = 0; i < 2; ++i) {
        int k = tid + i * 256;
        atomicMin(&g_center_min[k], colpk[k]);
    }
    if (tid == 0) {
        float s = 0.f;
        for (int i = 0; i < BM; ++i) s += loss_s[i];
        g_loss_partial[blockIdx.x] = s;
    }
}

// ---------------------------------------------------------------------------
// Finalize: deterministic loss reduction + centers copy + rep_ids
// out layout: [centers 512*128][rep_ids 512][loss 1]
// ---------------------------------------------------------------------------
__global__ void cl_fin_kernel(const float* __restrict__ C, float* __restrict__ out, int nb) {
    int b = blockIdx.x;
    int tid = threadIdx.x;
    if (b == 0) {
        __shared__ float s[256];
        float acc = 0.f;
        for (int i = tid; i < nb; i += 256) acc += g_loss_partial[i];
        s[tid] = acc;
        __syncthreads();
        if (tid == 0) {
            float tot = 0.f;
            for (int i = 0; i < 256; ++i) tot += s[i];
            out[KK * DD + KK] = tot;
        }
    } else if (b <= 256) {
        int idx = (b - 1) * 256 + tid;
        out[idx] = C[idx];
    } else {
        for (int k = tid; k < KK; k += 256) {
            out[KK * DD + k] =
                (float)(unsigned int)(g_center_min[k] & 0xFFFFFFFFULL);
        }
    }
}

// ---------------------------------------------------------------------------
extern "C" void kernel_launch(void* const* d_in, const int* in_sizes, int n_in,
                              void* d_out, int out_size) {
    const float* X = (const float*)d_in[0];
    const float* C = (const float*)d_in[1];
    float* out = (float*)d_out;

    int N = in_sizes[0] / DD;
    int nb = (N + BM - 1) / BM;

    cudaFuncSetAttribute(cl_main_kernel,
                         cudaFuncAttributeMaxDynamicSharedMemorySize, SMEM_BYTES);

    cl_init_kernel<<<128, 256>>>(C);
    cl_main_kernel<<<nb, THREADS, SMEM_BYTES>>>(X, N);
    cl_fin_kernel<<<258, 256>>>(C, out, nb);
}